// round 2
// baseline (speedup 1.0000x reference)
#include <cuda_runtime.h>

// Shapes (fixed by the problem)
#define NB 4
#define NT 2048
#define NC 1024
#define NH 16
#define ND 64
#define NBH (NB*NH)
#define SCALE 0.125f   // D^-0.5 = 1/8

// ---------------- scratch (device globals; no allocation allowed) ----------
__device__ float g_q[(size_t)NBH*NT*ND];        // 32 MB
__device__ float g_k[(size_t)NBH*NT*ND];        // 32 MB
__device__ float g_v[(size_t)NBH*NT*ND];        // 32 MB
__device__ float g_S[(size_t)NBH*NT*NT];        // 1 GiB scaled scores (lower-tri tiles only)
__device__ float g_colM[NBH*NT];                // per-column max
__device__ float g_colRZ[NBH*NT];               // per-column 1/sum
__device__ float g_att[(size_t)NB*NT*NC];       // concat-head attention output [B,T,H*D]

__device__ __forceinline__ float neg_inf() { return __int_as_float(0xff800000); }

// ============================================================================
// Kernel A: QKV projection.  out[b,h,t,d] = sum_c x[b,t,c] * W[h,c,d]
// grid = (T/128, 3, B*H), block 256.  Tile 128x64, BK=32, 8x4 per thread.
// ============================================================================
__global__ __launch_bounds__(256) void k_qkv(
    const float* __restrict__ x, const float* __restrict__ Wq,
    const float* __restrict__ Wk, const float* __restrict__ Wv)
{
    __shared__ float As[32][132];   // [k][m], padded: bank-conflict-free
    __shared__ float Bs[32][64];

    const int mt = blockIdx.x;
    const int which = blockIdx.y;
    const int bh = blockIdx.z;
    const int b = bh >> 4, h = bh & 15;

    const float* W;
    float* out;
    if (which == 0)      { W = Wq; out = g_q; }
    else if (which == 1) { W = Wk; out = g_k; }
    else                 { W = Wv; out = g_v; }
    W   += (size_t)h * NC * ND;
    out += (size_t)bh * NT * ND;

    const float* A = x + (size_t)b*NT*NC + (size_t)mt*128*NC;

    const int tid = threadIdx.x;
    const int tx = tid & 15;    // 16 col-groups * 4 cols
    const int ty = tid >> 4;    // 16 row-groups * 8 rows

    float acc[8][4];
    #pragma unroll
    for (int i = 0; i < 8; i++)
        #pragma unroll
        for (int j = 0; j < 4; j++) acc[i][j] = 0.f;

    for (int k0 = 0; k0 < NC; k0 += 32) {
        // A tile 128x32 -> transposed into As[k][m]
        #pragma unroll
        for (int r = 0; r < 4; r++) {
            int f = tid + 256*r;          // float4 index 0..1023
            int row = f >> 3;             // 8 float4 per row
            int kc  = (f & 7) << 2;
            float4 v4 = *(const float4*)(A + (size_t)row*NC + k0 + kc);
            As[kc+0][row] = v4.x; As[kc+1][row] = v4.y;
            As[kc+2][row] = v4.z; As[kc+3][row] = v4.w;
        }
        // B tile 32x64 (rows of W are contiguous D=64)
        #pragma unroll
        for (int r = 0; r < 2; r++) {
            int f = tid + 256*r;          // 0..511
            int row = f >> 4;             // 16 float4 per row
            int c4  = (f & 15) << 2;
            *(float4*)&Bs[row][c4] = *(const float4*)(W + (size_t)(k0+row)*ND + c4);
        }
        __syncthreads();
        #pragma unroll
        for (int kk = 0; kk < 32; kk++) {
            float4 a0 = *(float4*)&As[kk][ty*8];
            float4 a1 = *(float4*)&As[kk][ty*8+4];
            float4 b0 = *(float4*)&Bs[kk][tx*4];
            float a[8] = {a0.x,a0.y,a0.z,a0.w,a1.x,a1.y,a1.z,a1.w};
            float bb[4] = {b0.x,b0.y,b0.z,b0.w};
            #pragma unroll
            for (int i = 0; i < 8; i++)
                #pragma unroll
                for (int j = 0; j < 4; j++)
                    acc[i][j] = fmaf(a[i], bb[j], acc[i][j]);
        }
        __syncthreads();
    }
    #pragma unroll
    for (int i = 0; i < 8; i++) {
        int t = mt*128 + ty*8 + i;
        float4 o = make_float4(acc[i][0], acc[i][1], acc[i][2], acc[i][3]);
        *(float4*)(out + (size_t)t*ND + tx*4) = o;
    }
}

// ============================================================================
// Kernel B: scores S[t,s] = (s<=t) ? SCALE * dot(Q[t],K[s]) : -inf
// Only lower-triangular 128x128 tiles are computed/written.
// grid = (136 tri, 64 bh), block 256.  Tile 128x128, BK=16, 8x8 per thread.
// tri -> (ti, si) via triangular decode.
// ============================================================================
__global__ __launch_bounds__(256) void k_scores()
{
    // decode linear lower-tri index: tri = ti*(ti+1)/2 + si
    const int tri = blockIdx.x;
    int ti = (int)((sqrtf(8.0f*tri + 1.0f) - 1.0f) * 0.5f);
    while ((ti+1)*(ti+2)/2 <= tri) ti++;
    while (ti*(ti+1)/2 > tri) ti--;
    const int si = tri - ti*(ti+1)/2;
    const int bh = blockIdx.y;

    __shared__ float Qs[16][132];
    __shared__ float Ks[16][132];

    const float* Q = g_q + (size_t)bh*NT*ND + (size_t)ti*128*ND;
    const float* K = g_k + (size_t)bh*NT*ND + (size_t)si*128*ND;
    float* S = g_S + (size_t)bh*NT*NT;

    const int tid = threadIdx.x;
    const int tx = tid & 15, ty = tid >> 4;

    float acc[8][8];
    #pragma unroll
    for (int i = 0; i < 8; i++)
        #pragma unroll
        for (int j = 0; j < 8; j++) acc[i][j] = 0.f;

    for (int k0 = 0; k0 < ND; k0 += 16) {
        #pragma unroll
        for (int r = 0; r < 2; r++) {
            int f = tid + 256*r;          // 0..511 float4s of a 128x16 tile
            int row = f >> 2;             // 4 float4 per row
            int kc  = (f & 3) << 2;
            float4 q4 = *(const float4*)(Q + (size_t)row*ND + k0 + kc);
            Qs[kc+0][row]=q4.x; Qs[kc+1][row]=q4.y; Qs[kc+2][row]=q4.z; Qs[kc+3][row]=q4.w;
            float4 k4 = *(const float4*)(K + (size_t)row*ND + k0 + kc);
            Ks[kc+0][row]=k4.x; Ks[kc+1][row]=k4.y; Ks[kc+2][row]=k4.z; Ks[kc+3][row]=k4.w;
        }
        __syncthreads();
        #pragma unroll
        for (int kk = 0; kk < 16; kk++) {
            float4 a0 = *(float4*)&Qs[kk][ty*8];
            float4 a1 = *(float4*)&Qs[kk][ty*8+4];
            float4 b0 = *(float4*)&Ks[kk][tx*8];
            float4 b1 = *(float4*)&Ks[kk][tx*8+4];
            float a[8]  = {a0.x,a0.y,a0.z,a0.w,a1.x,a1.y,a1.z,a1.w};
            float bb[8] = {b0.x,b0.y,b0.z,b0.w,b1.x,b1.y,b1.z,b1.w};
            #pragma unroll
            for (int i = 0; i < 8; i++)
                #pragma unroll
                for (int j = 0; j < 8; j++)
                    acc[i][j] = fmaf(a[i], bb[j], acc[i][j]);
        }
        __syncthreads();
    }

    const int t0 = ti*128, s0 = si*128;
    #pragma unroll
    for (int i = 0; i < 8; i++) {
        int t = t0 + ty*8 + i;
        float o[8];
        #pragma unroll
        for (int j = 0; j < 8; j++) {
            int s = s0 + tx*8 + j;
            o[j] = (s <= t) ? acc[i][j] * SCALE : neg_inf();
        }
        *(float4*)(S + (size_t)t*NT + s0 + tx*8)     = make_float4(o[0],o[1],o[2],o[3]);
        *(float4*)(S + (size_t)t*NT + s0 + tx*8 + 4) = make_float4(o[4],o[5],o[6],o[7]);
    }
}

// ============================================================================
// Kernel C: per-COLUMN softmax stats over the query axis:
//   m[s] = max_{t>=s} S[t,s];  rZ[s] = 1 / sum_{t>=s} exp(S[t,s]-m[s])
// grid = (T/128, BH), block 256: 32 columns-of-float4 (=128 cols), 8 row-groups.
// Coalesced 128B rows across s; each thread owns 4 adjacent columns.
// ============================================================================
__global__ __launch_bounds__(256) void k_colstats()
{
    const int s0 = blockIdx.x * 128;
    const int bh = blockIdx.y;
    const int tid = threadIdx.x;
    const int c4 = (tid & 31) << 2;   // float4 column offset 0..124
    const int rg = tid >> 5;          // 0..7

    const float* Sb = g_S + (size_t)bh*NT*NT;
    float m[4] = {neg_inf(), neg_inf(), neg_inf(), neg_inf()};
    float z[4] = {0.f, 0.f, 0.f, 0.f};

    for (int t = s0 + rg; t < NT; t += 8) {
        float4 xv4 = *(const float4*)(Sb + (size_t)t*NT + s0 + c4);
        float xv[4] = {xv4.x, xv4.y, xv4.z, xv4.w};
        #pragma unroll
        for (int j = 0; j < 4; j++) {
            if (xv[j] != neg_inf()) {
                if (xv[j] > m[j]) { z[j] = z[j] * __expf(m[j] - xv[j]) + 1.0f; m[j] = xv[j]; }
                else              { z[j] += __expf(xv[j] - m[j]); }
            }
        }
    }
    __shared__ float rm[8][128], rz[8][128];
    #pragma unroll
    for (int j = 0; j < 4; j++) { rm[rg][c4+j] = m[j]; rz[rg][c4+j] = z[j]; }
    __syncthreads();
    if (tid < 128) {
        float M = rm[0][tid], Z = rz[0][tid];
        #pragma unroll
        for (int g = 1; g < 8; g++) {
            float m2 = rm[g][tid], z2 = rz[g][tid];
            if (m2 > M)               { Z = Z * __expf(M - m2) + z2; M = m2; }
            else if (m2 != neg_inf()) { Z += z2 * __expf(m2 - M); }
        }
        g_colM[bh*NT + s0 + tid]  = M;
        g_colRZ[bh*NT + s0 + tid] = 1.0f / Z;
    }
}

// ============================================================================
// Kernel D: att[b,t, h*64+d] = sum_{s<=t} exp(S[t,s]-m[s])*rZ[s] * V[s,d]
// grid = (16 ti, 64 bh), block 256.  Tile 128x64, BK=32 (only s-chunks <= t).
// ============================================================================
__global__ __launch_bounds__(256) void k_attv()
{
    const int ti = blockIdx.x;
    const int bh = blockIdx.y;
    const int b = bh >> 4, h = bh & 15;

    __shared__ float Ps[32][132];   // p transposed: [s_local][t_local]
    __shared__ float Vs[32][64];

    const float* S  = g_S + (size_t)bh*NT*NT + (size_t)ti*128*NT;
    const float* V  = g_v + (size_t)bh*NT*ND;
    const float* cm = g_colM  + bh*NT;
    const float* cz = g_colRZ + bh*NT;

    const int tid = threadIdx.x;
    const int tx = tid & 15, ty = tid >> 4;

    float acc[8][4];
    #pragma unroll
    for (int i = 0; i < 8; i++)
        #pragma unroll
        for (int j = 0; j < 4; j++) acc[i][j] = 0.f;

    const int nchunk = (ti + 1) * 4;     // covers s in [0, (ti+1)*128)
    for (int ck = 0; ck < nchunk; ck++) {
        int s0 = ck * 32;
        // P tile: 128 t-rows x 32 s-cols, generated from S on the fly
        #pragma unroll
        for (int r = 0; r < 4; r++) {
            int f = tid + 256*r;          // 0..1023 float4s
            int row = f >> 3;
            int sc  = (f & 7) << 2;
            float4 sv = *(const float4*)(S + (size_t)row*NT + s0 + sc);
            float4 m4 = *(const float4*)(cm + s0 + sc);
            float4 z4 = *(const float4*)(cz + s0 + sc);
            Ps[sc+0][row] = __expf(sv.x - m4.x) * z4.x;   // -inf -> exp -> 0
            Ps[sc+1][row] = __expf(sv.y - m4.y) * z4.y;
            Ps[sc+2][row] = __expf(sv.z - m4.z) * z4.z;
            Ps[sc+3][row] = __expf(sv.w - m4.w) * z4.w;
        }
        // V tile 32x64
        #pragma unroll
        for (int r = 0; r < 2; r++) {
            int f = tid + 256*r;
            int row = f >> 4;
            int c4  = (f & 15) << 2;
            *(float4*)&Vs[row][c4] = *(const float4*)(V + (size_t)(s0+row)*ND + c4);
        }
        __syncthreads();
        #pragma unroll
        for (int kk = 0; kk < 32; kk++) {
            float4 a0 = *(float4*)&Ps[kk][ty*8];
            float4 a1 = *(float4*)&Ps[kk][ty*8+4];
            float4 b0 = *(float4*)&Vs[kk][tx*4];
            float a[8]  = {a0.x,a0.y,a0.z,a0.w,a1.x,a1.y,a1.z,a1.w};
            float bb[4] = {b0.x,b0.y,b0.z,b0.w};
            #pragma unroll
            for (int i = 0; i < 8; i++)
                #pragma unroll
                for (int j = 0; j < 4; j++)
                    acc[i][j] = fmaf(a[i], bb[j], acc[i][j]);
        }
        __syncthreads();
    }
    #pragma unroll
    for (int i = 0; i < 8; i++) {
        int t = ti*128 + ty*8 + i;
        float4 o = make_float4(acc[i][0], acc[i][1], acc[i][2], acc[i][3]);
        *(float4*)(g_att + ((size_t)b*NT + t)*NC + h*ND + tx*4) = o;
    }
}

// ============================================================================
// Kernel E: out = att @ Wo + bo.   M=8192, N=1024, K=1024.
// grid = (64 mt, 8 nt), block 256. Tile 128x128, BK=16, 8x8 per thread.
// ============================================================================
__global__ __launch_bounds__(256) void k_outproj(
    const float* __restrict__ Wo, const float* __restrict__ bo,
    float* __restrict__ out)
{
    const int mt = blockIdx.x;
    const int nt = blockIdx.y;

    __shared__ float As[16][132];
    __shared__ float Bs[16][128];

    const float* A  = g_att + (size_t)mt*128*NC;
    const float* Bm = Wo + nt*128;

    const int tid = threadIdx.x;
    const int tx = tid & 15, ty = tid >> 4;

    float acc[8][8];
    #pragma unroll
    for (int i = 0; i < 8; i++)
        #pragma unroll
        for (int j = 0; j < 8; j++) acc[i][j] = 0.f;

    for (int k0 = 0; k0 < NC; k0 += 16) {
        #pragma unroll
        for (int r = 0; r < 2; r++) {
            int f = tid + 256*r;          // 0..511
            // A tile 128x16, transposed
            int row = f >> 2;
            int kc  = (f & 3) << 2;
            float4 a4 = *(const float4*)(A + (size_t)row*NC + k0 + kc);
            As[kc+0][row]=a4.x; As[kc+1][row]=a4.y; As[kc+2][row]=a4.z; As[kc+3][row]=a4.w;
            // B tile 16x128, direct
            int brow = f >> 5;            // 32 float4 per row
            int bc   = (f & 31) << 2;
            *(float4*)&Bs[brow][bc] = *(const float4*)(Bm + (size_t)(k0+brow)*NC + bc);
        }
        __syncthreads();
        #pragma unroll
        for (int kk = 0; kk < 16; kk++) {
            float4 a0 = *(float4*)&As[kk][ty*8];
            float4 a1 = *(float4*)&As[kk][ty*8+4];
            float4 b0 = *(float4*)&Bs[kk][tx*8];
            float4 b1 = *(float4*)&Bs[kk][tx*8+4];
            float a[8]  = {a0.x,a0.y,a0.z,a0.w,a1.x,a1.y,a1.z,a1.w};
            float bb[8] = {b0.x,b0.y,b0.z,b0.w,b1.x,b1.y,b1.z,b1.w};
            #pragma unroll
            for (int i = 0; i < 8; i++)
                #pragma unroll
                for (int j = 0; j < 8; j++)
                    acc[i][j] = fmaf(a[i], bb[j], acc[i][j]);
        }
        __syncthreads();
    }

    float4 bb0 = *(const float4*)(bo + nt*128 + tx*8);
    float4 bb1 = *(const float4*)(bo + nt*128 + tx*8 + 4);
    float bias[8] = {bb0.x,bb0.y,bb0.z,bb0.w,bb1.x,bb1.y,bb1.z,bb1.w};
    #pragma unroll
    for (int i = 0; i < 8; i++) {
        size_t m = (size_t)mt*128 + ty*8 + i;
        float4 o0 = make_float4(acc[i][0]+bias[0], acc[i][1]+bias[1],
                                acc[i][2]+bias[2], acc[i][3]+bias[3]);
        float4 o1 = make_float4(acc[i][4]+bias[4], acc[i][5]+bias[5],
                                acc[i][6]+bias[6], acc[i][7]+bias[7]);
        *(float4*)(out + m*NC + nt*128 + tx*8)     = o0;
        *(float4*)(out + m*NC + nt*128 + tx*8 + 4) = o1;
    }
}

// ============================================================================
extern "C" void kernel_launch(void* const* d_in, const int* in_sizes, int n_in,
                              void* d_out, int out_size)
{
    (void)in_sizes; (void)n_in; (void)out_size;
    const float* x  = (const float*)d_in[0];
    const float* Wq = (const float*)d_in[1];
    const float* Wk = (const float*)d_in[2];
    const float* Wv = (const float*)d_in[3];
    const float* Wo = (const float*)d_in[4];
    const float* bo = (const float*)d_in[5];
    float* out = (float*)d_out;

    k_qkv    <<<dim3(16, 3, NBH), 256>>>(x, Wq, Wk, Wv);
    k_scores <<<dim3(136, NBH), 256>>>();
    k_colstats<<<dim3(NT/128, NBH), 256>>>();
    k_attv   <<<dim3(16, NBH), 256>>>();
    k_outproj<<<dim3(64, 8), 256>>>(Wo, bo, out);
}

// round 3
// speedup vs baseline: 1.4790x; 1.4790x over previous
#include <cuda_runtime.h>

// Shapes (fixed by the problem)
#define NB 4
#define NT 2048
#define NC 1024
#define NH 16
#define ND 64
#define NBH (NB*NH)
#define SCALE 0.125f   // D^-0.5 = 1/8

// ---------------- scratch (device globals; no allocation allowed) ----------
__device__ float g_q[(size_t)NBH*NT*ND];        // 32 MB
__device__ float g_k[(size_t)NBH*NT*ND];        // 32 MB
__device__ float g_v[(size_t)NBH*NT*ND];        // 32 MB
__device__ float g_S[(size_t)NBH*NT*NT];        // 1 GiB scaled scores (lower-tri tiles only)
__device__ float g_colM[NBH*NT];                // per-column max
__device__ float g_colRZ[NBH*NT];               // per-column 1/sum
__device__ float g_att[(size_t)NB*NT*NC];       // concat-head attention output [B,T,H*D]

__device__ __forceinline__ float neg_inf() { return __int_as_float(0xff800000); }

// fp32 -> tf32 (round-to-nearest-even on the 10-bit mantissa), kept in b32 reg
__device__ __forceinline__ unsigned f2tf(float x) {
    unsigned r;
    asm("cvt.rna.tf32.f32 %0, %1;" : "=r"(r) : "f"(x));
    return r;
}

// D = A(16x8, row) * B(8x8, col) + D, tf32 inputs, fp32 accum
__device__ __forceinline__ void mma8(float* c, const unsigned* a, const unsigned* b) {
    asm volatile(
        "mma.sync.aligned.m16n8k8.row.col.f32.tf32.tf32.f32 "
        "{%0,%1,%2,%3}, {%4,%5,%6,%7}, {%8,%9}, {%0,%1,%2,%3};"
        : "+f"(c[0]), "+f"(c[1]), "+f"(c[2]), "+f"(c[3])
        : "r"(a[0]), "r"(a[1]), "r"(a[2]), "r"(a[3]), "r"(b[0]), "r"(b[1]));
}

// ============================================================================
// Kernel A: QKV projection.  out[b,h,t,d] = sum_c x[b,t,c] * W[h,c,d]
// grid = (T/128, 3, B*H), block 256 (8 warps as 4m x 2n, warp tile 32x32).
// Tensor: m16n8k8 tf32.  BK=32.
// ============================================================================
__global__ __launch_bounds__(256) void k_qkv(
    const float* __restrict__ x, const float* __restrict__ Wq,
    const float* __restrict__ Wk, const float* __restrict__ Wv)
{
    __shared__ unsigned As[32][132];   // [k][m] transposed, tf32 bits
    __shared__ unsigned Bs[32][68];    // [k][n], tf32 bits

    const int mt = blockIdx.x;
    const int which = blockIdx.y;
    const int bh = blockIdx.z;
    const int b = bh >> 4, h = bh & 15;

    const float* W;
    float* out;
    if (which == 0)      { W = Wq; out = g_q; }
    else if (which == 1) { W = Wk; out = g_k; }
    else                 { W = Wv; out = g_v; }
    W   += (size_t)h * NC * ND;
    out += (size_t)bh * NT * ND;

    const float* A = x + (size_t)b*NT*NC + (size_t)mt*128*NC;

    const int tid = threadIdx.x;
    const int lane = tid & 31, wid = tid >> 5;
    const int grp = lane >> 2, tig = lane & 3;
    const int m0w = (wid >> 1) * 32, n0w = (wid & 1) * 32;

    float acc[2][4][4];
    #pragma unroll
    for (int i = 0; i < 2; i++)
        #pragma unroll
        for (int j = 0; j < 4; j++)
            #pragma unroll
            for (int q = 0; q < 4; q++) acc[i][j][q] = 0.f;

    for (int k0 = 0; k0 < NC; k0 += 32) {
        // A tile 128x32 -> transposed As[k][m]
        #pragma unroll
        for (int r = 0; r < 4; r++) {
            int f = tid + 256*r;
            int row = f >> 3;
            int kc  = (f & 7) << 2;
            float4 v4 = *(const float4*)(A + (size_t)row*NC + k0 + kc);
            As[kc+0][row] = f2tf(v4.x); As[kc+1][row] = f2tf(v4.y);
            As[kc+2][row] = f2tf(v4.z); As[kc+3][row] = f2tf(v4.w);
        }
        // B tile 32x64 k-major
        #pragma unroll
        for (int r = 0; r < 2; r++) {
            int f = tid + 256*r;
            int row = f >> 4;
            int c4  = (f & 15) << 2;
            float4 w4 = *(const float4*)(W + (size_t)(k0+row)*ND + c4);
            Bs[row][c4+0] = f2tf(w4.x); Bs[row][c4+1] = f2tf(w4.y);
            Bs[row][c4+2] = f2tf(w4.z); Bs[row][c4+3] = f2tf(w4.w);
        }
        __syncthreads();
        #pragma unroll
        for (int ks = 0; ks < 4; ks++) {
            const int kc = ks * 8;
            unsigned a[2][4], bb[4][2];
            #pragma unroll
            for (int im = 0; im < 2; im++) {
                int m = m0w + im*16 + grp;
                a[im][0] = As[kc+tig][m];     a[im][1] = As[kc+tig][m+8];
                a[im][2] = As[kc+4+tig][m];   a[im][3] = As[kc+4+tig][m+8];
            }
            #pragma unroll
            for (int in_ = 0; in_ < 4; in_++) {
                int nn = n0w + in_*8 + grp;
                bb[in_][0] = Bs[kc+tig][nn];
                bb[in_][1] = Bs[kc+4+tig][nn];
            }
            #pragma unroll
            for (int im = 0; im < 2; im++)
                #pragma unroll
                for (int in_ = 0; in_ < 4; in_++)
                    mma8(acc[im][in_], a[im], bb[in_]);
        }
        __syncthreads();
    }
    #pragma unroll
    for (int im = 0; im < 2; im++)
        #pragma unroll
        for (int in_ = 0; in_ < 4; in_++) {
            int t = mt*128 + m0w + im*16 + grp;
            int d = n0w + in_*8 + 2*tig;
            *(float2*)(out + (size_t)t*ND + d)     = make_float2(acc[im][in_][0], acc[im][in_][1]);
            *(float2*)(out + (size_t)(t+8)*ND + d) = make_float2(acc[im][in_][2], acc[im][in_][3]);
        }
}

// ============================================================================
// Kernel B: scores S[t,s] = (s<=t) ? SCALE * dot(Q[t],K[s]) : -inf
// grid = (136 tri, 64 bh), block 256 (8 warps as 2m x 4n, warp tile 64x32).
// Tensor: m16n8k8 tf32.  BK=32, K=64.
// ============================================================================
__global__ __launch_bounds__(256) void k_scores()
{
    const int tri = blockIdx.x;
    int ti = (int)((sqrtf(8.0f*tri + 1.0f) - 1.0f) * 0.5f);
    while ((ti+1)*(ti+2)/2 <= tri) ti++;
    while (ti*(ti+1)/2 > tri) ti--;
    const int si = tri - ti*(ti+1)/2;
    const int bh = blockIdx.y;

    __shared__ unsigned Qs[32][132];
    __shared__ unsigned Ks[32][132];

    const float* Q = g_q + (size_t)bh*NT*ND + (size_t)ti*128*ND;
    const float* K = g_k + (size_t)bh*NT*ND + (size_t)si*128*ND;
    float* S = g_S + (size_t)bh*NT*NT;

    const int tid = threadIdx.x;
    const int lane = tid & 31, wid = tid >> 5;
    const int grp = lane >> 2, tig = lane & 3;
    const int m0w = (wid >> 2) * 64, n0w = (wid & 3) * 32;

    float acc[4][4][4];
    #pragma unroll
    for (int i = 0; i < 4; i++)
        #pragma unroll
        for (int j = 0; j < 4; j++)
            #pragma unroll
            for (int q = 0; q < 4; q++) acc[i][j][q] = 0.f;

    #pragma unroll
    for (int k0 = 0; k0 < ND; k0 += 32) {
        #pragma unroll
        for (int r = 0; r < 4; r++) {
            int f = tid + 256*r;
            int row = f >> 3;
            int kc  = (f & 7) << 2;
            float4 q4 = *(const float4*)(Q + (size_t)row*ND + k0 + kc);
            Qs[kc+0][row] = f2tf(q4.x); Qs[kc+1][row] = f2tf(q4.y);
            Qs[kc+2][row] = f2tf(q4.z); Qs[kc+3][row] = f2tf(q4.w);
            float4 k4 = *(const float4*)(K + (size_t)row*ND + k0 + kc);
            Ks[kc+0][row] = f2tf(k4.x); Ks[kc+1][row] = f2tf(k4.y);
            Ks[kc+2][row] = f2tf(k4.z); Ks[kc+3][row] = f2tf(k4.w);
        }
        __syncthreads();
        #pragma unroll
        for (int ks = 0; ks < 4; ks++) {
            const int kc = ks * 8;
            unsigned a[4][4], bb[4][2];
            #pragma unroll
            for (int im = 0; im < 4; im++) {
                int m = m0w + im*16 + grp;
                a[im][0] = Qs[kc+tig][m];     a[im][1] = Qs[kc+tig][m+8];
                a[im][2] = Qs[kc+4+tig][m];   a[im][3] = Qs[kc+4+tig][m+8];
            }
            #pragma unroll
            for (int in_ = 0; in_ < 4; in_++) {
                int nn = n0w + in_*8 + grp;
                bb[in_][0] = Ks[kc+tig][nn];
                bb[in_][1] = Ks[kc+4+tig][nn];
            }
            #pragma unroll
            for (int im = 0; im < 4; im++)
                #pragma unroll
                for (int in_ = 0; in_ < 4; in_++)
                    mma8(acc[im][in_], a[im], bb[in_]);
        }
        __syncthreads();
    }

    const int t0 = ti*128, s0 = si*128;
    const float NI = neg_inf();
    #pragma unroll
    for (int im = 0; im < 4; im++)
        #pragma unroll
        for (int in_ = 0; in_ < 4; in_++) {
            int t = t0 + m0w + im*16 + grp;
            int s = s0 + n0w + in_*8 + 2*tig;
            float v0 = (s   <= t) ? acc[im][in_][0] * SCALE : NI;
            float v1 = (s+1 <= t) ? acc[im][in_][1] * SCALE : NI;
            *(float2*)(S + (size_t)t*NT + s) = make_float2(v0, v1);
            int t2 = t + 8;
            float v2 = (s   <= t2) ? acc[im][in_][2] * SCALE : NI;
            float v3 = (s+1 <= t2) ? acc[im][in_][3] * SCALE : NI;
            *(float2*)(S + (size_t)t2*NT + s) = make_float2(v2, v3);
        }
}

// ============================================================================
// Kernel C: per-COLUMN softmax stats (query-axis softmax):
//   m[s] = max_{t>=s} S[t,s];  rZ[s] = 1 / sum_{t>=s} exp(S[t,s]-m[s])
// grid = (T/128, BH), block 256.  (memory-bound; unchanged)
// ============================================================================
__global__ __launch_bounds__(256) void k_colstats()
{
    const int s0 = blockIdx.x * 128;
    const int bh = blockIdx.y;
    const int tid = threadIdx.x;
    const int c4 = (tid & 31) << 2;
    const int rg = tid >> 5;

    const float* Sb = g_S + (size_t)bh*NT*NT;
    float m[4] = {neg_inf(), neg_inf(), neg_inf(), neg_inf()};
    float z[4] = {0.f, 0.f, 0.f, 0.f};

    for (int t = s0 + rg; t < NT; t += 8) {
        float4 xv4 = *(const float4*)(Sb + (size_t)t*NT + s0 + c4);
        float xv[4] = {xv4.x, xv4.y, xv4.z, xv4.w};
        #pragma unroll
        for (int j = 0; j < 4; j++) {
            if (xv[j] != neg_inf()) {
                if (xv[j] > m[j]) { z[j] = z[j] * __expf(m[j] - xv[j]) + 1.0f; m[j] = xv[j]; }
                else              { z[j] += __expf(xv[j] - m[j]); }
            }
        }
    }
    __shared__ float rm[8][128], rz[8][128];
    #pragma unroll
    for (int j = 0; j < 4; j++) { rm[rg][c4+j] = m[j]; rz[rg][c4+j] = z[j]; }
    __syncthreads();
    if (tid < 128) {
        float M = rm[0][tid], Z = rz[0][tid];
        #pragma unroll
        for (int g = 1; g < 8; g++) {
            float m2 = rm[g][tid], z2 = rz[g][tid];
            if (m2 > M)               { Z = Z * __expf(M - m2) + z2; M = m2; }
            else if (m2 != neg_inf()) { Z += z2 * __expf(m2 - M); }
        }
        g_colM[bh*NT + s0 + tid]  = M;
        g_colRZ[bh*NT + s0 + tid] = 1.0f / Z;
    }
}

// ============================================================================
// Kernel D: att[b,t, h*64+d] = sum_{s<=t} exp(S[t,s]-m[s])*rZ[s] * V[s,d]
// grid = (16 ti, 64 bh), block 256 (8 warps as 4m x 2n, warp tile 32x32).
// Tensor: m16n8k8 tf32.  BK=32, only s-chunks <= t.
// ============================================================================
__global__ __launch_bounds__(256) void k_attv()
{
    const int ti = blockIdx.x;
    const int bh = blockIdx.y;
    const int b = bh >> 4, h = bh & 15;

    __shared__ unsigned Ps[32][132];   // P transposed [s_local][t_local], tf32
    __shared__ unsigned Vs[32][68];    // [s_local][d], tf32

    const float* S  = g_S + (size_t)bh*NT*NT + (size_t)ti*128*NT;
    const float* V  = g_v + (size_t)bh*NT*ND;
    const float* cm = g_colM  + bh*NT;
    const float* cz = g_colRZ + bh*NT;

    const int tid = threadIdx.x;
    const int lane = tid & 31, wid = tid >> 5;
    const int grp = lane >> 2, tig = lane & 3;
    const int m0w = (wid >> 1) * 32, n0w = (wid & 1) * 32;

    float acc[2][4][4];
    #pragma unroll
    for (int i = 0; i < 2; i++)
        #pragma unroll
        for (int j = 0; j < 4; j++)
            #pragma unroll
            for (int q = 0; q < 4; q++) acc[i][j][q] = 0.f;

    const int nchunk = (ti + 1) * 4;
    for (int ck = 0; ck < nchunk; ck++) {
        int s0 = ck * 32;
        // P tile: 128 t-rows x 32 s-cols, generated from S on the fly
        #pragma unroll
        for (int r = 0; r < 4; r++) {
            int f = tid + 256*r;
            int row = f >> 3;
            int sc  = (f & 7) << 2;
            float4 sv = *(const float4*)(S + (size_t)row*NT + s0 + sc);
            float4 m4 = *(const float4*)(cm + s0 + sc);
            float4 z4 = *(const float4*)(cz + s0 + sc);
            Ps[sc+0][row] = f2tf(__expf(sv.x - m4.x) * z4.x);   // -inf -> 0
            Ps[sc+1][row] = f2tf(__expf(sv.y - m4.y) * z4.y);
            Ps[sc+2][row] = f2tf(__expf(sv.z - m4.z) * z4.z);
            Ps[sc+3][row] = f2tf(__expf(sv.w - m4.w) * z4.w);
        }
        // V tile 32x64
        #pragma unroll
        for (int r = 0; r < 2; r++) {
            int f = tid + 256*r;
            int row = f >> 4;
            int c4  = (f & 15) << 2;
            float4 v4 = *(const float4*)(V + (size_t)(s0+row)*ND + c4);
            Vs[row][c4+0] = f2tf(v4.x); Vs[row][c4+1] = f2tf(v4.y);
            Vs[row][c4+2] = f2tf(v4.z); Vs[row][c4+3] = f2tf(v4.w);
        }
        __syncthreads();
        #pragma unroll
        for (int ks = 0; ks < 4; ks++) {
            const int kc = ks * 8;
            unsigned a[2][4], bb[4][2];
            #pragma unroll
            for (int im = 0; im < 2; im++) {
                int m = m0w + im*16 + grp;
                a[im][0] = Ps[kc+tig][m];     a[im][1] = Ps[kc+tig][m+8];
                a[im][2] = Ps[kc+4+tig][m];   a[im][3] = Ps[kc+4+tig][m+8];
            }
            #pragma unroll
            for (int in_ = 0; in_ < 4; in_++) {
                int nn = n0w + in_*8 + grp;
                bb[in_][0] = Vs[kc+tig][nn];
                bb[in_][1] = Vs[kc+4+tig][nn];
            }
            #pragma unroll
            for (int im = 0; im < 2; im++)
                #pragma unroll
                for (int in_ = 0; in_ < 4; in_++)
                    mma8(acc[im][in_], a[im], bb[in_]);
        }
        __syncthreads();
    }
    #pragma unroll
    for (int im = 0; im < 2; im++)
        #pragma unroll
        for (int in_ = 0; in_ < 4; in_++) {
            int t = ti*128 + m0w + im*16 + grp;
            int d = n0w + in_*8 + 2*tig;
            *(float2*)(g_att + ((size_t)b*NT + t)*NC + h*ND + d) =
                make_float2(acc[im][in_][0], acc[im][in_][1]);
            *(float2*)(g_att + ((size_t)b*NT + t + 8)*NC + h*ND + d) =
                make_float2(acc[im][in_][2], acc[im][in_][3]);
        }
}

// ============================================================================
// Kernel E: out = att @ Wo + bo.   M=8192, N=1024, K=1024.
// grid = (64 mt, 8 nt), block 256 (8 warps as 2m x 4n, warp tile 64x32).
// Tensor: m16n8k8 tf32.  BK=32.
// ============================================================================
__global__ __launch_bounds__(256) void k_outproj(
    const float* __restrict__ Wo, const float* __restrict__ bo,
    float* __restrict__ out)
{
    const int mt = blockIdx.x;
    const int nt = blockIdx.y;

    __shared__ unsigned As[32][132];
    __shared__ unsigned Bs[32][132];

    const float* A  = g_att + (size_t)mt*128*NC;
    const float* Bm = Wo + nt*128;

    const int tid = threadIdx.x;
    const int lane = tid & 31, wid = tid >> 5;
    const int grp = lane >> 2, tig = lane & 3;
    const int m0w = (wid >> 2) * 64, n0w = (wid & 3) * 32;

    float acc[4][4][4];
    #pragma unroll
    for (int i = 0; i < 4; i++)
        #pragma unroll
        for (int j = 0; j < 4; j++)
            #pragma unroll
            for (int q = 0; q < 4; q++) acc[i][j][q] = 0.f;

    for (int k0 = 0; k0 < NC; k0 += 32) {
        #pragma unroll
        for (int r = 0; r < 4; r++) {
            int f = tid + 256*r;
            // A tile 128x32, transposed
            int row = f >> 3;
            int kc  = (f & 7) << 2;
            float4 a4 = *(const float4*)(A + (size_t)row*NC + k0 + kc);
            As[kc+0][row] = f2tf(a4.x); As[kc+1][row] = f2tf(a4.y);
            As[kc+2][row] = f2tf(a4.z); As[kc+3][row] = f2tf(a4.w);
            // B tile 32x128, k-major direct
            int brow = f >> 5;
            int bc   = (f & 31) << 2;
            float4 w4 = *(const float4*)(Bm + (size_t)(k0+brow)*NC + bc);
            Bs[brow][bc+0] = f2tf(w4.x); Bs[brow][bc+1] = f2tf(w4.y);
            Bs[brow][bc+2] = f2tf(w4.z); Bs[brow][bc+3] = f2tf(w4.w);
        }
        __syncthreads();
        #pragma unroll
        for (int ks = 0; ks < 4; ks++) {
            const int kc = ks * 8;
            unsigned a[4][4], bb[4][2];
            #pragma unroll
            for (int im = 0; im < 4; im++) {
                int m = m0w + im*16 + grp;
                a[im][0] = As[kc+tig][m];     a[im][1] = As[kc+tig][m+8];
                a[im][2] = As[kc+4+tig][m];   a[im][3] = As[kc+4+tig][m+8];
            }
            #pragma unroll
            for (int in_ = 0; in_ < 4; in_++) {
                int nn = n0w + in_*8 + grp;
                bb[in_][0] = Bs[kc+tig][nn];
                bb[in_][1] = Bs[kc+4+tig][nn];
            }
            #pragma unroll
            for (int im = 0; im < 4; im++)
                #pragma unroll
                for (int in_ = 0; in_ < 4; in_++)
                    mma8(acc[im][in_], a[im], bb[in_]);
        }
        __syncthreads();
    }

    #pragma unroll
    for (int im = 0; im < 4; im++)
        #pragma unroll
        for (int in_ = 0; in_ < 4; in_++) {
            size_t m = (size_t)mt*128 + m0w + im*16 + grp;
            int col = n0w + in_*8 + 2*tig;
            float b0v = bo[nt*128 + col], b1v = bo[nt*128 + col + 1];
            *(float2*)(out + m*NC + nt*128 + col) =
                make_float2(acc[im][in_][0] + b0v, acc[im][in_][1] + b1v);
            *(float2*)(out + (m+8)*NC + nt*128 + col) =
                make_float2(acc[im][in_][2] + b0v, acc[im][in_][3] + b1v);
        }
}

// ============================================================================
extern "C" void kernel_launch(void* const* d_in, const int* in_sizes, int n_in,
                              void* d_out, int out_size)
{
    (void)in_sizes; (void)n_in; (void)out_size;
    const float* x  = (const float*)d_in[0];
    const float* Wq = (const float*)d_in[1];
    const float* Wk = (const float*)d_in[2];
    const float* Wv = (const float*)d_in[3];
    const float* Wo = (const float*)d_in[4];
    const float* bo = (const float*)d_in[5];
    float* out = (float*)d_out;

    k_qkv     <<<dim3(16, 3, NBH), 256>>>(x, Wq, Wk, Wv);
    k_scores  <<<dim3(136, NBH), 256>>>();
    k_colstats<<<dim3(NT/128, NBH), 256>>>();
    k_attv    <<<dim3(16, NBH), 256>>>();
    k_outproj <<<dim3(64, 8), 256>>>(Wo, bo, out);
}

// round 5
// speedup vs baseline: 2.0425x; 1.3809x over previous
#include <cuda_runtime.h>

// Shapes (fixed by the problem)
#define NB 4
#define NT 2048
#define NC 1024
#define NH 16
#define ND 64
#define NBH (NB*NH)
#define SCALE 0.125f   // D^-0.5 = 1/8

// ---------------- scratch (device globals; no allocation allowed) ----------
__device__ __align__(128) float g_q[(size_t)NBH*NT*ND];
__device__ __align__(128) float g_k[(size_t)NBH*NT*ND];
__device__ __align__(128) float g_v[(size_t)NBH*NT*ND];
__device__ __align__(128) float g_S[(size_t)NBH*NT*NT];   // scores -> probabilities (in place)
__device__ __align__(128) float g_att[(size_t)NB*NT*NC];

__device__ __forceinline__ float neg_inf() { return __int_as_float(0xff800000); }

__device__ __forceinline__ unsigned f2tf(float x) {
    unsigned r;
    asm("cvt.rna.tf32.f32 %0, %1;" : "=r"(r) : "f"(x));
    return r;
}

__device__ __forceinline__ void mma8(float* c, const unsigned* a, const unsigned* b) {
    asm volatile(
        "mma.sync.aligned.m16n8k8.row.col.f32.tf32.tf32.f32 "
        "{%0,%1,%2,%3}, {%4,%5,%6,%7}, {%8,%9}, {%0,%1,%2,%3};"
        : "+f"(c[0]), "+f"(c[1]), "+f"(c[2]), "+f"(c[3])
        : "r"(a[0]), "r"(a[1]), "r"(a[2]), "r"(a[3]), "r"(b[0]), "r"(b[1]));
}

// ---------------- cp.async helpers ----------------
__device__ __forceinline__ void cpa16(void* smem_dst, const void* gmem_src) {
    unsigned s = (unsigned)__cvta_generic_to_shared(smem_dst);
    asm volatile("cp.async.ca.shared.global [%0], [%1], 16;\n" :: "r"(s), "l"(gmem_src) : "memory");
}
__device__ __forceinline__ void cp_commit() { asm volatile("cp.async.commit_group;\n" ::: "memory"); }
template<int N> __device__ __forceinline__ void cp_wait() {
    asm volatile("cp.async.wait_group %0;\n" :: "n"(N) : "memory");
}

// ---------------- dynamic smem layouts ----------------
struct SmemQKV { float As[2][128][36]; float Bs[2][32][68]; };   // 54.2 KB
struct SmemSc  { float Qs[128][68];    float Ks[128][68];   };   // 69.6 KB
struct SmemAtt { float As[2][128][36]; float Vs[2][32][68]; };   // 54.2 KB
struct SmemOut { float As[2][128][36]; float Bs[2][32][132];};   // 70.7 KB

// ============================================================================
// Kernel A: QKV projection. out[b,h,t,d] = sum_c x[b,t,c]*W[h,c,d]
// block 256 (8 warps 4m x 2n, warp 32x32). BK=32, cp.async double-buffered.
// ============================================================================
__global__ __launch_bounds__(256) void k_qkv(
    const float* __restrict__ x, const float* __restrict__ Wq,
    const float* __restrict__ Wk, const float* __restrict__ Wv)
{
    extern __shared__ char smraw[];
    SmemQKV& sm = *reinterpret_cast<SmemQKV*>(smraw);

    const int mt = blockIdx.x;
    const int which = blockIdx.y;
    const int bh = blockIdx.z;
    const int b = bh >> 4, h = bh & 15;

    const float* W;
    float* out;
    if (which == 0)      { W = Wq; out = g_q; }
    else if (which == 1) { W = Wk; out = g_k; }
    else                 { W = Wv; out = g_v; }
    W   += (size_t)h * NC * ND;
    out += (size_t)bh * NT * ND;

    const float* A = x + (size_t)b*NT*NC + (size_t)mt*128*NC;

    const int tid = threadIdx.x;
    const int lane = tid & 31, wid = tid >> 5;
    const int grp = lane >> 2, tig = lane & 3;
    const int m0w = (wid >> 1) * 32, n0w = (wid & 1) * 32;

    auto loadA = [&](int buf, int k0) {
        #pragma unroll
        for (int r = 0; r < 4; r++) {
            int f = tid + 256*r;
            int row = f >> 3, c4 = (f & 7) << 2;
            cpa16(&sm.As[buf][row][c4], A + (size_t)row*NC + k0 + c4);
        }
    };
    auto loadB = [&](int buf, int k0) {
        #pragma unroll
        for (int r = 0; r < 2; r++) {
            int f = tid + 256*r;
            int row = f >> 4, c4 = (f & 15) << 2;
            cpa16(&sm.Bs[buf][row][c4], W + (size_t)(k0+row)*ND + c4);
        }
    };

    float acc[2][4][4];
    #pragma unroll
    for (int i = 0; i < 2; i++)
        #pragma unroll
        for (int j = 0; j < 4; j++)
            #pragma unroll
            for (int q = 0; q < 4; q++) acc[i][j][q] = 0.f;

    loadA(0, 0); loadB(0, 0); cp_commit();

    const int NCH = NC / 32;
    for (int ck = 0; ck < NCH; ck++) {
        int buf = ck & 1;
        if (ck + 1 < NCH) { loadA(buf^1, (ck+1)*32); loadB(buf^1, (ck+1)*32); cp_commit(); cp_wait<1>(); }
        else              { cp_wait<0>(); }
        __syncthreads();
        #pragma unroll
        for (int ks = 0; ks < 4; ks++) {
            const int kc = ks * 8;
            unsigned a[2][4], bb[4][2];
            #pragma unroll
            for (int im = 0; im < 2; im++) {
                int m = m0w + im*16 + grp;
                a[im][0] = f2tf(sm.As[buf][m  ][kc+tig]);
                a[im][1] = f2tf(sm.As[buf][m+8][kc+tig]);
                a[im][2] = f2tf(sm.As[buf][m  ][kc+tig+4]);
                a[im][3] = f2tf(sm.As[buf][m+8][kc+tig+4]);
            }
            #pragma unroll
            for (int in_ = 0; in_ < 4; in_++) {
                int nn = n0w + in_*8 + grp;
                bb[in_][0] = f2tf(sm.Bs[buf][kc+tig  ][nn]);
                bb[in_][1] = f2tf(sm.Bs[buf][kc+tig+4][nn]);
            }
            #pragma unroll
            for (int im = 0; im < 2; im++) {
                #pragma unroll
                for (int in_ = 0; in_ < 4; in_++)
                    mma8(acc[im][in_], a[im], bb[in_]);
            }
        }
        __syncthreads();
    }
    #pragma unroll
    for (int im = 0; im < 2; im++) {
        #pragma unroll
        for (int in_ = 0; in_ < 4; in_++) {
            int t = mt*128 + m0w + im*16 + grp;
            int d = n0w + in_*8 + 2*tig;
            *(float2*)(out + (size_t)t*ND + d)     = make_float2(acc[im][in_][0], acc[im][in_][1]);
            *(float2*)(out + (size_t)(t+8)*ND + d) = make_float2(acc[im][in_][2], acc[im][in_][3]);
        }
    }
}

// ============================================================================
// Kernel B: scores S[t,s] = (s<=t) ? SCALE*dot(Q[t],K[s]) : -inf
// block 256 (8 warps 2m x 4n, warp 64x32). Whole K=64 in smem, single stage.
// ============================================================================
__global__ __launch_bounds__(256) void k_scores()
{
    extern __shared__ char smraw[];
    SmemSc& sm = *reinterpret_cast<SmemSc*>(smraw);

    const int tri = blockIdx.x;
    int ti = (int)((sqrtf(8.0f*tri + 1.0f) - 1.0f) * 0.5f);
    while ((ti+1)*(ti+2)/2 <= tri) ti++;
    while (ti*(ti+1)/2 > tri) ti--;
    const int si = tri - ti*(ti+1)/2;
    const int bh = blockIdx.y;

    const float* Q = g_q + (size_t)bh*NT*ND + (size_t)ti*128*ND;
    const float* K = g_k + (size_t)bh*NT*ND + (size_t)si*128*ND;
    float* S = g_S + (size_t)bh*NT*NT;

    const int tid = threadIdx.x;
    const int lane = tid & 31, wid = tid >> 5;
    const int grp = lane >> 2, tig = lane & 3;
    const int m0w = (wid >> 2) * 64, n0w = (wid & 3) * 32;

    #pragma unroll
    for (int r = 0; r < 8; r++) {
        int f = tid + 256*r;
        int row = f >> 4, c4 = (f & 15) << 2;
        cpa16(&sm.Qs[row][c4], Q + (size_t)row*ND + c4);
        cpa16(&sm.Ks[row][c4], K + (size_t)row*ND + c4);
    }
    cp_commit(); cp_wait<0>();
    __syncthreads();

    float acc[4][4][4];
    #pragma unroll
    for (int i = 0; i < 4; i++)
        #pragma unroll
        for (int j = 0; j < 4; j++)
            #pragma unroll
            for (int q = 0; q < 4; q++) acc[i][j][q] = 0.f;

    #pragma unroll
    for (int ks = 0; ks < 8; ks++) {
        const int kc = ks * 8;
        unsigned a[4][4], bb[4][2];
        #pragma unroll
        for (int im = 0; im < 4; im++) {
            int m = m0w + im*16 + grp;
            a[im][0] = f2tf(sm.Qs[m  ][kc+tig]);
            a[im][1] = f2tf(sm.Qs[m+8][kc+tig]);
            a[im][2] = f2tf(sm.Qs[m  ][kc+tig+4]);
            a[im][3] = f2tf(sm.Qs[m+8][kc+tig+4]);
        }
        #pragma unroll
        for (int in_ = 0; in_ < 4; in_++) {
            int nn = n0w + in_*8 + grp;
            bb[in_][0] = f2tf(sm.Ks[nn][kc+tig]);
            bb[in_][1] = f2tf(sm.Ks[nn][kc+tig+4]);
        }
        #pragma unroll
        for (int im = 0; im < 4; im++) {
            #pragma unroll
            for (int in_ = 0; in_ < 4; in_++)
                mma8(acc[im][in_], a[im], bb[in_]);
        }
    }

    const int t0 = ti*128, s0 = si*128;
    const float NI = neg_inf();
    #pragma unroll
    for (int im = 0; im < 4; im++) {
        #pragma unroll
        for (int in_ = 0; in_ < 4; in_++) {
            int t = t0 + m0w + im*16 + grp;
            int s = s0 + n0w + in_*8 + 2*tig;
            float v0 = (s   <= t) ? acc[im][in_][0] * SCALE : NI;
            float v1 = (s+1 <= t) ? acc[im][in_][1] * SCALE : NI;
            *(float2*)(S + (size_t)t*NT + s) = make_float2(v0, v1);
            int t2 = t + 8;
            float v2 = (s   <= t2) ? acc[im][in_][2] * SCALE : NI;
            float v3 = (s+1 <= t2) ? acc[im][in_][3] * SCALE : NI;
            *(float2*)(S + (size_t)t2*NT + s) = make_float2(v2, v3);
        }
    }
}

// ============================================================================
// Kernel C: column stats (softmax over query axis) + IN-PLACE S -> P
//   m[s]=max_{t>=s}S[t,s]; rZ[s]=1/sum exp(S-m); then S[t,s]=exp(S-m)*rZ.
// grid=(T/128, BH), block 256.
// ============================================================================
__global__ __launch_bounds__(256) void k_colstats()
{
    const int s0 = blockIdx.x * 128;
    const int bh = blockIdx.y;
    const int tid = threadIdx.x;
    const int c4 = (tid & 31) << 2;
    const int rg = tid >> 5;

    float* Sb = g_S + (size_t)bh*NT*NT;
    float m[4] = {neg_inf(), neg_inf(), neg_inf(), neg_inf()};
    float z[4] = {0.f, 0.f, 0.f, 0.f};

    for (int t = s0 + rg; t < NT; t += 8) {
        float4 xv4 = *(const float4*)(Sb + (size_t)t*NT + s0 + c4);
        float xv[4] = {xv4.x, xv4.y, xv4.z, xv4.w};
        #pragma unroll
        for (int j = 0; j < 4; j++) {
            if (xv[j] != neg_inf()) {
                if (xv[j] > m[j]) { z[j] = z[j] * __expf(m[j] - xv[j]) + 1.0f; m[j] = xv[j]; }
                else              { z[j] += __expf(xv[j] - m[j]); }
            }
        }
    }
    __shared__ float rm[8][128], rz[8][128];
    __shared__ float fM[128], fRZ[128];
    #pragma unroll
    for (int j = 0; j < 4; j++) { rm[rg][c4+j] = m[j]; rz[rg][c4+j] = z[j]; }
    __syncthreads();
    if (tid < 128) {
        float M = rm[0][tid], Z = rz[0][tid];
        #pragma unroll
        for (int g = 1; g < 8; g++) {
            float m2 = rm[g][tid], z2 = rz[g][tid];
            if (m2 > M)               { Z = Z * __expf(M - m2) + z2; M = m2; }
            else if (m2 != neg_inf()) { Z += z2 * __expf(m2 - M); }
        }
        fM[tid] = M; fRZ[tid] = 1.0f / Z;
    }
    __syncthreads();

    // in-place transform: S -> P   (exp(-inf - M) = 0 handles the mask)
    const float4 M4  = *(const float4*)&fM[c4];
    const float4 RZ4 = *(const float4*)&fRZ[c4];
    for (int t = s0 + rg; t < NT; t += 8) {
        float* p = Sb + (size_t)t*NT + s0 + c4;
        float4 xv = *(const float4*)p;
        xv.x = __expf(xv.x - M4.x) * RZ4.x;
        xv.y = __expf(xv.y - M4.y) * RZ4.y;
        xv.z = __expf(xv.z - M4.z) * RZ4.z;
        xv.w = __expf(xv.w - M4.w) * RZ4.w;
        *(float4*)p = xv;
    }
}

// ============================================================================
// Kernel D: att = P @ V (pure tf32 GEMM; P already normalized, in g_S).
// block 256 (8 warps 4m x 2n). BK=32, cp.async double-buffered.
// ============================================================================
__global__ __launch_bounds__(256) void k_attv()
{
    extern __shared__ char smraw[];
    SmemAtt& sm = *reinterpret_cast<SmemAtt*>(smraw);

    const int ti = blockIdx.x;
    const int bh = blockIdx.y;
    const int b = bh >> 4, h = bh & 15;

    const float* P = g_S + (size_t)bh*NT*NT + (size_t)ti*128*NT;
    const float* V = g_v + (size_t)bh*NT*ND;

    const int tid = threadIdx.x;
    const int lane = tid & 31, wid = tid >> 5;
    const int grp = lane >> 2, tig = lane & 3;
    const int m0w = (wid >> 1) * 32, n0w = (wid & 1) * 32;

    auto loadP = [&](int buf, int s0) {
        #pragma unroll
        for (int r = 0; r < 4; r++) {
            int f = tid + 256*r;
            int row = f >> 3, c4 = (f & 7) << 2;
            cpa16(&sm.As[buf][row][c4], P + (size_t)row*NT + s0 + c4);
        }
    };
    auto loadV = [&](int buf, int s0) {
        #pragma unroll
        for (int r = 0; r < 2; r++) {
            int f = tid + 256*r;
            int row = f >> 4, c4 = (f & 15) << 2;
            cpa16(&sm.Vs[buf][row][c4], V + (size_t)(s0+row)*ND + c4);
        }
    };

    float acc[2][4][4];
    #pragma unroll
    for (int i = 0; i < 2; i++)
        #pragma unroll
        for (int j = 0; j < 4; j++)
            #pragma unroll
            for (int q = 0; q < 4; q++) acc[i][j][q] = 0.f;

    const int nchunk = (ti + 1) * 4;
    loadP(0, 0); loadV(0, 0); cp_commit();

    for (int ck = 0; ck < nchunk; ck++) {
        int buf = ck & 1;
        if (ck + 1 < nchunk) { loadP(buf^1, (ck+1)*32); loadV(buf^1, (ck+1)*32); cp_commit(); cp_wait<1>(); }
        else                 { cp_wait<0>(); }
        __syncthreads();
        #pragma unroll
        for (int ks = 0; ks < 4; ks++) {
            const int kc = ks * 8;
            unsigned a[2][4], bb[4][2];
            #pragma unroll
            for (int im = 0; im < 2; im++) {
                int m = m0w + im*16 + grp;
                a[im][0] = f2tf(sm.As[buf][m  ][kc+tig]);
                a[im][1] = f2tf(sm.As[buf][m+8][kc+tig]);
                a[im][2] = f2tf(sm.As[buf][m  ][kc+tig+4]);
                a[im][3] = f2tf(sm.As[buf][m+8][kc+tig+4]);
            }
            #pragma unroll
            for (int in_ = 0; in_ < 4; in_++) {
                int nn = n0w + in_*8 + grp;
                bb[in_][0] = f2tf(sm.Vs[buf][kc+tig  ][nn]);
                bb[in_][1] = f2tf(sm.Vs[buf][kc+tig+4][nn]);
            }
            #pragma unroll
            for (int im = 0; im < 2; im++) {
                #pragma unroll
                for (int in_ = 0; in_ < 4; in_++)
                    mma8(acc[im][in_], a[im], bb[in_]);
            }
        }
        __syncthreads();
    }
    #pragma unroll
    for (int im = 0; im < 2; im++) {
        #pragma unroll
        for (int in_ = 0; in_ < 4; in_++) {
            int t = ti*128 + m0w + im*16 + grp;
            int d = n0w + in_*8 + 2*tig;
            *(float2*)(g_att + ((size_t)b*NT + t)*NC + h*ND + d) =
                make_float2(acc[im][in_][0], acc[im][in_][1]);
            *(float2*)(g_att + ((size_t)b*NT + t + 8)*NC + h*ND + d) =
                make_float2(acc[im][in_][2], acc[im][in_][3]);
        }
    }
}

// ============================================================================
// Kernel E: out = att @ Wo + bo.  M=8192,N=1024,K=1024.
// block 256 (8 warps 2m x 4n). BK=32, cp.async double-buffered.
// ============================================================================
__global__ __launch_bounds__(256) void k_outproj(
    const float* __restrict__ Wo, const float* __restrict__ bo,
    float* __restrict__ out)
{
    extern __shared__ char smraw[];
    SmemOut& sm = *reinterpret_cast<SmemOut*>(smraw);

    const int mt = blockIdx.x;
    const int nt = blockIdx.y;

    const float* A  = g_att + (size_t)mt*128*NC;
    const float* Bm = Wo + nt*128;

    const int tid = threadIdx.x;
    const int lane = tid & 31, wid = tid >> 5;
    const int grp = lane >> 2, tig = lane & 3;
    const int m0w = (wid >> 2) * 64, n0w = (wid & 3) * 32;

    auto loadA = [&](int buf, int k0) {
        #pragma unroll
        for (int r = 0; r < 4; r++) {
            int f = tid + 256*r;
            int row = f >> 3, c4 = (f & 7) << 2;
            cpa16(&sm.As[buf][row][c4], A + (size_t)row*NC + k0 + c4);
        }
    };
    auto loadB = [&](int buf, int k0) {
        #pragma unroll
        for (int r = 0; r < 4; r++) {
            int f = tid + 256*r;
            int row = f >> 5, c4 = (f & 31) << 2;
            cpa16(&sm.Bs[buf][row][c4], Bm + (size_t)(k0+row)*NC + c4);
        }
    };

    float acc[4][4][4];
    #pragma unroll
    for (int i = 0; i < 4; i++)
        #pragma unroll
        for (int j = 0; j < 4; j++)
            #pragma unroll
            for (int q = 0; q < 4; q++) acc[i][j][q] = 0.f;

    loadA(0, 0); loadB(0, 0); cp_commit();

    const int NCH = NC / 32;
    for (int ck = 0; ck < NCH; ck++) {
        int buf = ck & 1;
        if (ck + 1 < NCH) { loadA(buf^1, (ck+1)*32); loadB(buf^1, (ck+1)*32); cp_commit(); cp_wait<1>(); }
        else              { cp_wait<0>(); }
        __syncthreads();
        #pragma unroll
        for (int ks = 0; ks < 4; ks++) {
            const int kc = ks * 8;
            unsigned a[4][4], bb[4][2];
            #pragma unroll
            for (int im = 0; im < 4; im++) {
                int m = m0w + im*16 + grp;
                a[im][0] = f2tf(sm.As[buf][m  ][kc+tig]);
                a[im][1] = f2tf(sm.As[buf][m+8][kc+tig]);
                a[im][2] = f2tf(sm.As[buf][m  ][kc+tig+4]);
                a[im][3] = f2tf(sm.As[buf][m+8][kc+tig+4]);
            }
            #pragma unroll
            for (int in_ = 0; in_ < 4; in_++) {
                int nn = n0w + in_*8 + grp;
                bb[in_][0] = f2tf(sm.Bs[buf][kc+tig  ][nn]);
                bb[in_][1] = f2tf(sm.Bs[buf][kc+tig+4][nn]);
            }
            #pragma unroll
            for (int im = 0; im < 4; im++) {
                #pragma unroll
                for (int in_ = 0; in_ < 4; in_++)
                    mma8(acc[im][in_], a[im], bb[in_]);
            }
        }
        __syncthreads();
    }

    #pragma unroll
    for (int im = 0; im < 4; im++) {
        #pragma unroll
        for (int in_ = 0; in_ < 4; in_++) {
            size_t m = (size_t)mt*128 + m0w + im*16 + grp;
            int col = n0w + in_*8 + 2*tig;
            float b0v = bo[nt*128 + col], b1v = bo[nt*128 + col + 1];
            *(float2*)(out + m*NC + nt*128 + col) =
                make_float2(acc[im][in_][0] + b0v, acc[im][in_][1] + b1v);
            *(float2*)(out + (m+8)*NC + nt*128 + col) =
                make_float2(acc[im][in_][2] + b0v, acc[im][in_][3] + b1v);
        }
    }
}

// ============================================================================
extern "C" void kernel_launch(void* const* d_in, const int* in_sizes, int n_in,
                              void* d_out, int out_size)
{
    (void)in_sizes; (void)n_in; (void)out_size;
    const float* x  = (const float*)d_in[0];
    const float* Wq = (const float*)d_in[1];
    const float* Wk = (const float*)d_in[2];
    const float* Wv = (const float*)d_in[3];
    const float* Wo = (const float*)d_in[4];
    const float* bo = (const float*)d_in[5];
    float* out = (float*)d_out;

    cudaFuncSetAttribute(k_qkv,     cudaFuncAttributeMaxDynamicSharedMemorySize, (int)sizeof(SmemQKV));
    cudaFuncSetAttribute(k_scores,  cudaFuncAttributeMaxDynamicSharedMemorySize, (int)sizeof(SmemSc));
    cudaFuncSetAttribute(k_attv,    cudaFuncAttributeMaxDynamicSharedMemorySize, (int)sizeof(SmemAtt));
    cudaFuncSetAttribute(k_outproj, cudaFuncAttributeMaxDynamicSharedMemorySize, (int)sizeof(SmemOut));

    k_qkv     <<<dim3(16, 3, NBH), 256, sizeof(SmemQKV)>>>(x, Wq, Wk, Wv);
    k_scores  <<<dim3(136, NBH),   256, sizeof(SmemSc)>>>();
    k_colstats<<<dim3(NT/128, NBH), 256>>>();
    k_attv    <<<dim3(16, NBH),    256, sizeof(SmemAtt)>>>();
    k_outproj <<<dim3(64, 8),      256, sizeof(SmemOut)>>>(Wo, bo, out);
}